// round 9
// baseline (speedup 1.0000x reference)
#include <cuda_runtime.h>
#include <cuda_fp16.h>
#include <cstdint>
#include <cstddef>

#define MTOT 8192
#define KTOT 4096
#define NTOT 16384

#define BM 128
#define BN 256
#define BK 128
#define KIT (KTOT / BK)            // 32
#define ASTRIDE 272                // 256B row + 16B pad (conflict-free)
#define A_STAGE (128 * ASTRIDE)    // 34816
#define B_STAGE (256 * ASTRIDE)    // 69632
#define STG_B (A_STAGE + B_STAGE)  // 104448
#define SMEM_TOTAL (2 * STG_B)     // 208896

// ---------------- scratch ----------------
__device__ __half g_xh[(size_t)MTOT * KTOT];
__device__ __half g_wh[(size_t)NTOT * KTOT];

// ---------------- PTX helpers ----------------
__device__ __forceinline__ uint32_t smem_u32(const void* p) {
    uint32_t a;
    asm("{ .reg .u64 t; cvta.to.shared.u64 t, %1; cvt.u32.u64 %0, t; }" : "=r"(a) : "l"(p));
    return a;
}
#define CP16(dst, src) \
    asm volatile("cp.async.cg.shared.global [%0], [%1], 16;" :: "r"(dst), "l"(src) : "memory")
#define CP_COMMIT() asm volatile("cp.async.commit_group;" ::: "memory")
#define CP_WAIT(n)  asm volatile("cp.async.wait_group %0;" :: "n"(n) : "memory")

__device__ __forceinline__ void ldsm_x4(uint32_t* r, uint32_t addr) {
    asm volatile("ldmatrix.sync.aligned.m8n8.x4.shared.b16 {%0,%1,%2,%3}, [%4];"
                 : "=r"(r[0]), "=r"(r[1]), "=r"(r[2]), "=r"(r[3]) : "r"(addr));
}
__device__ __forceinline__ void mma_f16(float* d, const uint32_t* a, const uint32_t* b) {
    asm volatile(
        "mma.sync.aligned.m16n8k16.row.col.f32.f16.f16.f32 "
        "{%0,%1,%2,%3}, {%4,%5,%6,%7}, {%8,%9}, {%0,%1,%2,%3};"
        : "+f"(d[0]), "+f"(d[1]), "+f"(d[2]), "+f"(d[3])
        : "r"(a[0]), "r"(a[1]), "r"(a[2]), "r"(a[3]), "r"(b[0]), "r"(b[1]));
}

// ---------------- kernel 1: x fp32 -> fp16 ----------------
__global__ void __launch_bounds__(256) cx_kernel(const float* __restrict__ x) {
    size_t idx = (size_t)blockIdx.x * 256 + threadIdx.x;
    const float4* xi = (const float4*)x;
    float4 v0 = xi[idx * 2];
    float4 v1 = xi[idx * 2 + 1];
    __half2 h[4];
    h[0] = __float22half2_rn(make_float2(v0.x, v0.y));
    h[1] = __float22half2_rn(make_float2(v0.z, v0.w));
    h[2] = __float22half2_rn(make_float2(v1.x, v1.y));
    h[3] = __float22half2_rn(make_float2(v1.z, v1.w));
    ((uint4*)g_xh)[idx] = *(uint4*)h;
}

// ---------------- kernel 2: W int32 -> fp16 (exact) ----------------
__global__ void __launch_bounds__(256) cw_kernel(const int* __restrict__ wq) {
    size_t idx = (size_t)blockIdx.x * 256 + threadIdx.x;
    const int4* wi = (const int4*)wq;
    int4 v0 = wi[idx * 2];
    int4 v1 = wi[idx * 2 + 1];
    __half h[8];
    h[0] = __int2half_rn(v0.x); h[1] = __int2half_rn(v0.y);
    h[2] = __int2half_rn(v0.z); h[3] = __int2half_rn(v0.w);
    h[4] = __int2half_rn(v1.x); h[5] = __int2half_rn(v1.y);
    h[6] = __int2half_rn(v1.z); h[7] = __int2half_rn(v1.w);
    ((uint4*)g_wh)[idx] = *(uint4*)h;
}

// ---------------- kernel 3: fp16 HMMA GEMM, BK=128, 2-stage, reg-dbuf ----------------
__global__ void __launch_bounds__(256, 1) gemm_kernel(
    float* __restrict__ out, const float* __restrict__ wscale,
    const float* __restrict__ bias)
{
    extern __shared__ uint8_t smem[];

    int tid = threadIdx.x;
    int wid = tid >> 5;
    int lane = tid & 31;
    int wm = wid >> 2;          // 0..1 (64 m rows)
    int wn = wid & 3;           // 0..3 (64 n cols)

    // GM=8 M-grouped raster over 64(m) x 64(n) tile grid
    int gid = blockIdx.x;
    int group = gid >> 9;
    int rem = gid & 511;
    int pid_m = group * 8 + (rem & 7);
    int pid_n = rem >> 3;

    const __half* Ab = g_xh + (size_t)pid_m * BM * KTOT;
    const __half* Bb = g_wh + (size_t)pid_n * BN * KTOT;

    uint32_t smem0 = smem_u32(smem);

    // cp.async one stage: A 2048 chunks (8/thr), B 4096 chunks (16/thr)
    auto issue = [&](int it) {
        uint32_t st = smem0 + (it & 1) * STG_B;
        int k0 = it * BK;
        int row = tid >> 4;          // 0..15
        int col = tid & 15;          // 0..15 (16B chunks across 256B row)
        const __half* Asrc = Ab + (size_t)row * KTOT + k0 + col * 8;
        const __half* Bsrc = Bb + (size_t)row * KTOT + k0 + col * 8;
        uint32_t Adst = st + row * ASTRIDE + col * 16;
        uint32_t Bdst = st + A_STAGE + row * ASTRIDE + col * 16;
#pragma unroll
        for (int j = 0; j < 8; j++)
            CP16(Adst + j * 16 * ASTRIDE, Asrc + (size_t)j * 16 * KTOT);
#pragma unroll
        for (int j = 0; j < 16; j++)
            CP16(Bdst + j * 16 * ASTRIDE, Bsrc + (size_t)j * 16 * KTOT);
    };

    issue(0); CP_COMMIT();
    issue(1); CP_COMMIT();

    float acc[4][8][4];
#pragma unroll
    for (int f = 0; f < 4; f++)
#pragma unroll
        for (int g = 0; g < 8; g++)
#pragma unroll
            for (int e = 0; e < 4; e++) acc[f][g][e] = 0.f;

    int j8 = lane >> 3;
    int r8 = lane & 7;
    int a_row = wm * 64 + (j8 & 1) * 8 + r8;
    int a_koff = (j8 >> 1) * 16;
    int b_row = wn * 64 + (j8 >> 1) * 8 + r8;
    int b_koff = (j8 & 1) * 16;

    uint32_t a[2][4][4], b[2][4][4];

    auto ldfrags = [&](int slot, uint32_t aB, uint32_t bB, int ks) {
#pragma unroll
        for (int f = 0; f < 4; f++)
            ldsm_x4(a[slot][f], aB + (a_row + f * 16) * ASTRIDE + ks * 32 + a_koff);
#pragma unroll
        for (int gg = 0; gg < 4; gg++)
            ldsm_x4(b[slot][gg], bB + (b_row + gg * 16) * ASTRIDE + ks * 32 + b_koff);
    };

    // prologue: stage 0 ready
    CP_WAIT(1);
    __syncthreads();
    ldfrags(0, smem0, smem0 + A_STAGE, 0);

    int cur = 0;
    for (int it = 0; it < KIT; it++) {
        uint32_t aB = smem0 + (it & 1) * STG_B;
        uint32_t bB = aB + A_STAGE;

#pragma unroll
        for (int ks = 0; ks < 8; ks++) {
            if (ks < 7) ldfrags(cur ^ 1, aB, bB, ks + 1);
#pragma unroll
            for (int g = 0; g < 8; g++)
#pragma unroll
                for (int f = 0; f < 4; f++)
                    mma_f16(acc[f][g], a[cur][f], b[cur][g >> 1] + (g & 1) * 2);
            if (ks < 7) cur ^= 1;
        }

        __syncthreads();                    // all warps done reading stage it&1
        if (it + 2 < KIT) issue(it + 2);    // refill the buffer just freed
        CP_COMMIT();                        // unconditional: keeps group counting sound
        if (it + 1 < KIT) {
            CP_WAIT(1);                     // stage (it+1)&1 ready
            __syncthreads();                // make it visible to all warps
            uint32_t aB2 = smem0 + ((it + 1) & 1) * STG_B;
            ldfrags(cur ^ 1, aB2, aB2 + A_STAGE, 0);
            cur ^= 1;
        }
    }

    // ---------------- epilogue: dequant + bias ----------------
    int lr = lane >> 2;
    int lc2 = (lane & 3) * 2;
#pragma unroll
    for (int f = 0; f < 4; f++) {
        int gm = pid_m * BM + wm * 64 + f * 16 + lr;
        float* o0 = out + (size_t)gm * NTOT + pid_n * BN;
        float* o1 = o0 + (size_t)8 * NTOT;
#pragma unroll
        for (int g = 0; g < 8; g++) {
            int nc = wn * 64 + g * 8 + lc2;
            int gn = pid_n * BN + nc;
            float w0 = __ldg(wscale + gn), w1 = __ldg(wscale + gn + 1);
            float b0 = __ldg(bias + gn),   b1 = __ldg(bias + gn + 1);
            float2 r0, r1;
            r0.x = fmaf(acc[f][g][0], w0, b0);
            r0.y = fmaf(acc[f][g][1], w1, b1);
            r1.x = fmaf(acc[f][g][2], w0, b0);
            r1.y = fmaf(acc[f][g][3], w1, b1);
            *(float2*)(o0 + nc) = r0;
            *(float2*)(o1 + nc) = r1;
        }
    }
}

// ---------------- launch ----------------
extern "C" void kernel_launch(void* const* d_in, const int* in_sizes, int n_in,
                              void* d_out, int out_size) {
    const float* x      = (const float*)d_in[0];
    const int*   wq     = (const int*)d_in[1];
    const float* wscale = (const float*)d_in[2];
    const float* bias   = (const float*)d_in[3];
    float* out = (float*)d_out;

    cudaFuncSetAttribute(gemm_kernel, cudaFuncAttributeMaxDynamicSharedMemorySize, SMEM_TOTAL);

    cx_kernel<<<(int)((size_t)MTOT * KTOT / 8 / 256), 256>>>(x);
    cw_kernel<<<(int)((size_t)NTOT * KTOT / 8 / 256), 256>>>(wq);
    gemm_kernel<<<4096, 256, SMEM_TOTAL>>>(out, wscale, bias);
}

// round 10
// speedup vs baseline: 1.9445x; 1.9445x over previous
#include <cuda_runtime.h>
#include <cuda_fp16.h>
#include <cstdint>
#include <cstddef>

#define MTOT 8192
#define KTOT 4096
#define NTOT 16384

#define BM 128
#define BN 256
#define BK 64
#define STAGES 4
#define KIT (KTOT / BK)            // 64
#define ASTRIDE 144
#define A_STAGE (128 * ASTRIDE)
#define B_STAGE (256 * ASTRIDE)
#define STG_B (A_STAGE + B_STAGE)
#define SMEM_TOTAL (STAGES * STG_B)

// ---------------- scratch ----------------
__device__ __half g_xh[(size_t)MTOT * KTOT];
__device__ __half g_wh[(size_t)NTOT * KTOT];

// ---------------- PTX helpers ----------------
__device__ __forceinline__ uint32_t smem_u32(const void* p) {
    uint32_t a;
    asm("{ .reg .u64 t; cvta.to.shared.u64 t, %1; cvt.u32.u64 %0, t; }" : "=r"(a) : "l"(p));
    return a;
}
#define CP16(dst, src) \
    asm volatile("cp.async.cg.shared.global [%0], [%1], 16;" :: "r"(dst), "l"(src) : "memory")
#define CP_COMMIT() asm volatile("cp.async.commit_group;" ::: "memory")
#define CP_WAIT(n)  asm volatile("cp.async.wait_group %0;" :: "n"(n) : "memory")

__device__ __forceinline__ void ldsm_x4(uint32_t* r, uint32_t addr) {
    asm volatile("ldmatrix.sync.aligned.m8n8.x4.shared.b16 {%0,%1,%2,%3}, [%4];"
                 : "=r"(r[0]), "=r"(r[1]), "=r"(r[2]), "=r"(r[3]) : "r"(addr));
}
__device__ __forceinline__ void mma_f16(float* d, const uint32_t* a, const uint32_t* b) {
    asm volatile(
        "mma.sync.aligned.m16n8k16.row.col.f32.f16.f16.f32 "
        "{%0,%1,%2,%3}, {%4,%5,%6,%7}, {%8,%9}, {%0,%1,%2,%3};"
        : "+f"(d[0]), "+f"(d[1]), "+f"(d[2]), "+f"(d[3])
        : "r"(a[0]), "r"(a[1]), "r"(a[2]), "r"(a[3]), "r"(b[0]), "r"(b[1]));
}

// ---------------- fused preprocessing: x fp32->fp16 and W int32->fp16 ----------------
// blocks [0, 16384): x (8 fp32 -> 8 fp16 per thread)
// blocks [16384, 49152): W (8 int32 -> 8 fp16 per thread)
__global__ void __launch_bounds__(256) conv_kernel(
    const float* __restrict__ x, const int* __restrict__ wq)
{
    int bid = blockIdx.x;
    if (bid < 16384) {
        size_t idx = (size_t)bid * 256 + threadIdx.x;
        const float4* xi = (const float4*)x;
        float4 v0 = xi[idx * 2];
        float4 v1 = xi[idx * 2 + 1];
        __half2 h[4];
        h[0] = __float22half2_rn(make_float2(v0.x, v0.y));
        h[1] = __float22half2_rn(make_float2(v0.z, v0.w));
        h[2] = __float22half2_rn(make_float2(v1.x, v1.y));
        h[3] = __float22half2_rn(make_float2(v1.z, v1.w));
        ((uint4*)g_xh)[idx] = *(uint4*)h;
    } else {
        size_t idx = (size_t)(bid - 16384) * 256 + threadIdx.x;
        const int4* wi = (const int4*)wq;
        int4 v0 = wi[idx * 2];
        int4 v1 = wi[idx * 2 + 1];
        __half h[8];
        h[0] = __int2half_rn(v0.x); h[1] = __int2half_rn(v0.y);
        h[2] = __int2half_rn(v0.z); h[3] = __int2half_rn(v0.w);
        h[4] = __int2half_rn(v1.x); h[5] = __int2half_rn(v1.y);
        h[6] = __int2half_rn(v1.z); h[7] = __int2half_rn(v1.w);
        ((uint4*)g_wh)[idx] = *(uint4*)h;
    }
}

// ---------------- GEMM: fp16 HMMA, 8 warps, 64x64 warptile, reg-dbuf frags ----------------
__global__ void __launch_bounds__(256, 1) gemm_kernel(
    float* __restrict__ out, const float* __restrict__ wscale,
    const float* __restrict__ bias)
{
    extern __shared__ uint8_t smem[];

    int tid = threadIdx.x;
    int wid = tid >> 5;
    int lane = tid & 31;
    int wm = wid >> 2;
    int wn = wid & 3;

    int gid = blockIdx.x;
    int group = gid >> 9;
    int rem = gid & 511;
    int pid_m = group * 8 + (rem & 7);
    int pid_n = rem >> 3;

    const __half* Ab = g_xh + (size_t)pid_m * BM * KTOT;
    const __half* Bb = g_wh + (size_t)pid_n * BN * KTOT;

    uint32_t smem0 = smem_u32(smem);

    auto issue = [&](int it) {
        uint32_t st = smem0 + (it % STAGES) * STG_B;
        int k0 = it * BK;
        const __half* Asrc = Ab + (size_t)(tid >> 3) * KTOT + k0 + (tid & 7) * 8;
        const __half* Bsrc = Bb + (size_t)(tid >> 3) * KTOT + k0 + (tid & 7) * 8;
        uint32_t Adst = st + (tid >> 3) * ASTRIDE + (tid & 7) * 16;
        uint32_t Bdst = st + A_STAGE + (tid >> 3) * ASTRIDE + (tid & 7) * 16;
#pragma unroll
        for (int j = 0; j < 4; j++)
            CP16(Adst + j * 32 * ASTRIDE, Asrc + (size_t)j * 32 * KTOT);
#pragma unroll
        for (int j = 0; j < 8; j++)
            CP16(Bdst + j * 32 * ASTRIDE, Bsrc + (size_t)j * 32 * KTOT);
    };

#pragma unroll
    for (int s = 0; s < STAGES - 1; s++) {
        issue(s);
        CP_COMMIT();
    }

    float acc[4][8][4];
#pragma unroll
    for (int f = 0; f < 4; f++)
#pragma unroll
        for (int g = 0; g < 8; g++)
#pragma unroll
            for (int e = 0; e < 4; e++) acc[f][g][e] = 0.f;

    int j8 = lane >> 3;
    int r8 = lane & 7;
    int a_row = wm * 64 + (j8 & 1) * 8 + r8;
    int a_koff = (j8 >> 1) * 16;
    int b_row = wn * 64 + (j8 >> 1) * 8 + r8;
    int b_koff = (j8 & 1) * 16;

    uint32_t a[2][4][4], b[2][4][4];

    auto ldfrags = [&](int slot, uint32_t aB, uint32_t bB, int ks) {
#pragma unroll
        for (int f = 0; f < 4; f++)
            ldsm_x4(a[slot][f], aB + (a_row + f * 16) * ASTRIDE + ks * 32 + a_koff);
#pragma unroll
        for (int gg = 0; gg < 4; gg++)
            ldsm_x4(b[slot][gg], bB + (b_row + gg * 16) * ASTRIDE + ks * 32 + b_koff);
    };

    // prologue: stage 0 ready, load ks=0 frags
    CP_WAIT(STAGES - 2);
    __syncthreads();
    {
        uint32_t aB = smem0;
        ldfrags(0, aB, aB + A_STAGE, 0);
    }

    int cur = 0;
    for (int it = 0; it < KIT; it++) {
        uint32_t aB = smem0 + (it % STAGES) * STG_B;
        uint32_t bB = aB + A_STAGE;

#pragma unroll
        for (int ks = 0; ks < 4; ks++) {
            int nxt = cur ^ 1;
            if (ks < 3) {
                ldfrags(nxt, aB, bB, ks + 1);
            } else if (it + 1 < KIT) {
                CP_WAIT(STAGES - 2);
                __syncthreads();
                if (it + STAGES - 1 < KIT) issue(it + STAGES - 1);
                CP_COMMIT();
                uint32_t aB2 = smem0 + ((it + 1) % STAGES) * STG_B;
                ldfrags(nxt, aB2, aB2 + A_STAGE, 0);
            }
#pragma unroll
            for (int g = 0; g < 8; g++)
#pragma unroll
                for (int f = 0; f < 4; f++)
                    mma_f16(acc[f][g], a[cur][f], b[cur][g >> 1] + (g & 1) * 2);
            cur = nxt;
        }
    }

    // ---------------- epilogue: dequant + bias ----------------
    int lr = lane >> 2;
    int lc2 = (lane & 3) * 2;
#pragma unroll
    for (int f = 0; f < 4; f++) {
        int gm = pid_m * BM + wm * 64 + f * 16 + lr;
        float* o0 = out + (size_t)gm * NTOT + pid_n * BN;
        float* o1 = o0 + (size_t)8 * NTOT;
#pragma unroll
        for (int g = 0; g < 8; g++) {
            int nc = wn * 64 + g * 8 + lc2;
            int gn = pid_n * BN + nc;
            float w0 = __ldg(wscale + gn), w1 = __ldg(wscale + gn + 1);
            float b0 = __ldg(bias + gn),   b1 = __ldg(bias + gn + 1);
            float2 r0, r1;
            r0.x = fmaf(acc[f][g][0], w0, b0);
            r0.y = fmaf(acc[f][g][1], w1, b1);
            r1.x = fmaf(acc[f][g][2], w0, b0);
            r1.y = fmaf(acc[f][g][3], w1, b1);
            *(float2*)(o0 + nc) = r0;
            *(float2*)(o1 + nc) = r1;
        }
    }
}

// ---------------- launch ----------------
extern "C" void kernel_launch(void* const* d_in, const int* in_sizes, int n_in,
                              void* d_out, int out_size) {
    const float* x      = (const float*)d_in[0];
    const int*   wq     = (const int*)d_in[1];
    const float* wscale = (const float*)d_in[2];
    const float* bias   = (const float*)d_in[3];
    float* out = (float*)d_out;

    cudaFuncSetAttribute(gemm_kernel, cudaFuncAttributeMaxDynamicSharedMemorySize, SMEM_TOTAL);

    conv_kernel<<<49152, 256>>>(x, wq);
    gemm_kernel<<<4096, 256, SMEM_TOTAL>>>(out, wscale, bias);
}

// round 12
// speedup vs baseline: 2.3161x; 1.1911x over previous
#include <cuda_runtime.h>
#include <cuda_fp16.h>
#include <cstdint>
#include <cstddef>

#define MTOT 8192
#define KTOT 4096
#define NTOT 16384

#define BM 128
#define BN 128
#define BK 64
#define STAGES 3
#define KIT (KTOT / BK)            // 64
#define ASTRIDE 144
#define A_STAGE (128 * ASTRIDE)
#define B_STAGE (128 * ASTRIDE)
#define STG_B (A_STAGE + B_STAGE)  // 36864
#define SMEM_TOTAL (STAGES * STG_B) // 110592 per CTA, x2 CTAs/SM

// ---------------- scratch ----------------
__device__ __half g_xh[(size_t)MTOT * KTOT];
__device__ __half g_wh[(size_t)NTOT * KTOT];

// ---------------- PTX helpers ----------------
__device__ __forceinline__ uint32_t smem_u32(const void* p) {
    uint32_t a;
    asm("{ .reg .u64 t; cvta.to.shared.u64 t, %1; cvt.u32.u64 %0, t; }" : "=r"(a) : "l"(p));
    return a;
}
#define CP16(dst, src) \
    asm volatile("cp.async.cg.shared.global [%0], [%1], 16;" :: "r"(dst), "l"(src) : "memory")
#define CP_COMMIT() asm volatile("cp.async.commit_group;" ::: "memory")
#define CP_WAIT(n)  asm volatile("cp.async.wait_group %0;" :: "n"(n) : "memory")

__device__ __forceinline__ void ldsm_x4(uint32_t* r, uint32_t addr) {
    asm volatile("ldmatrix.sync.aligned.m8n8.x4.shared.b16 {%0,%1,%2,%3}, [%4];"
                 : "=r"(r[0]), "=r"(r[1]), "=r"(r[2]), "=r"(r[3]) : "r"(addr));
}
__device__ __forceinline__ void mma_f16(float* d, const uint32_t* a, const uint32_t* b) {
    asm volatile(
        "mma.sync.aligned.m16n8k16.row.col.f32.f16.f16.f32 "
        "{%0,%1,%2,%3}, {%4,%5,%6,%7}, {%8,%9}, {%0,%1,%2,%3};"
        : "+f"(d[0]), "+f"(d[1]), "+f"(d[2]), "+f"(d[3])
        : "r"(a[0]), "r"(a[1]), "r"(a[2]), "r"(a[3]), "r"(b[0]), "r"(b[1]));
}

// ---------------- fused preprocessing ----------------
__global__ void __launch_bounds__(256) conv_kernel(
    const float* __restrict__ x, const int* __restrict__ wq)
{
    int bid = blockIdx.x;
    if (bid < 16384) {
        size_t idx = (size_t)bid * 256 + threadIdx.x;
        const float4* xi = (const float4*)x;
        float4 v0 = xi[idx * 2];
        float4 v1 = xi[idx * 2 + 1];
        __half2 h[4];
        h[0] = __float22half2_rn(make_float2(v0.x, v0.y));
        h[1] = __float22half2_rn(make_float2(v0.z, v0.w));
        h[2] = __float22half2_rn(make_float2(v1.x, v1.y));
        h[3] = __float22half2_rn(make_float2(v1.z, v1.w));
        ((uint4*)g_xh)[idx] = *(uint4*)h;
    } else {
        size_t idx = (size_t)(bid - 16384) * 256 + threadIdx.x;
        const int4* wi = (const int4*)wq;
        int4 v0 = wi[idx * 2];
        int4 v1 = wi[idx * 2 + 1];
        __half h[8];
        h[0] = __int2half_rn(v0.x); h[1] = __int2half_rn(v0.y);
        h[2] = __int2half_rn(v0.z); h[3] = __int2half_rn(v0.w);
        h[4] = __int2half_rn(v1.x); h[5] = __int2half_rn(v1.y);
        h[6] = __int2half_rn(v1.z); h[7] = __int2half_rn(v1.w);
        ((uint4*)g_wh)[idx] = *(uint4*)h;
    }
}

// ---------------- GEMM: 128x128, 2 CTAs/SM, reg-dbuf frags, sound pipeline ----------------
__global__ void __launch_bounds__(256, 2) gemm_kernel(
    float* __restrict__ out, const float* __restrict__ wscale,
    const float* __restrict__ bias)
{
    extern __shared__ uint8_t smem[];

    int tid = threadIdx.x;
    int wid = tid >> 5;
    int lane = tid & 31;
    int wm = wid >> 2;          // 0..1 (64 m rows)
    int wn = wid & 3;           // 0..3 (32 n cols)

    // GM=8 M-grouped raster over 64(m) x 128(n) tile grid
    int gid = blockIdx.x;
    int group = gid >> 10;
    int rem = gid & 1023;
    int pid_m = group * 8 + (rem & 7);
    int pid_n = rem >> 3;

    const __half* Ab = g_xh + (size_t)pid_m * BM * KTOT;
    const __half* Bb = g_wh + (size_t)pid_n * BN * KTOT;

    uint32_t smem0 = smem_u32(smem);

    // cp.async one stage: A 1024 chunks + B 1024 chunks, 8 per thread
    auto issue = [&](int it) {
        uint32_t st = smem0 + (it % STAGES) * STG_B;
        int k0 = it * BK;
        int row = tid >> 3;
        int col = tid & 7;
        const __half* Asrc = Ab + (size_t)row * KTOT + k0 + col * 8;
        const __half* Bsrc = Bb + (size_t)row * KTOT + k0 + col * 8;
        uint32_t Adst = st + row * ASTRIDE + col * 16;
        uint32_t Bdst = st + A_STAGE + row * ASTRIDE + col * 16;
#pragma unroll
        for (int j = 0; j < 4; j++)
            CP16(Adst + j * 32 * ASTRIDE, Asrc + (size_t)j * 32 * KTOT);
#pragma unroll
        for (int j = 0; j < 4; j++)
            CP16(Bdst + j * 32 * ASTRIDE, Bsrc + (size_t)j * 32 * KTOT);
    };

    // prologue: issue stages 0,1
    issue(0); CP_COMMIT();
    issue(1); CP_COMMIT();

    float acc[4][4][4];
#pragma unroll
    for (int f = 0; f < 4; f++)
#pragma unroll
        for (int g = 0; g < 4; g++)
#pragma unroll
            for (int e = 0; e < 4; e++) acc[f][g][e] = 0.f;

    int j8 = lane >> 3;
    int r8 = lane & 7;
    int a_row = wm * 64 + (j8 & 1) * 8 + r8;
    int a_koff = (j8 >> 1) * 16;
    int b_row = wn * 32 + (j8 >> 1) * 8 + r8;
    int b_koff = (j8 & 1) * 16;

    uint32_t a[2][4][4], b[2][2][4];

    auto ldfrags = [&](int slot, uint32_t aB, uint32_t bB, int ks) {
#pragma unroll
        for (int f = 0; f < 4; f++)
            ldsm_x4(a[slot][f], aB + (a_row + f * 16) * ASTRIDE + ks * 32 + a_koff);
#pragma unroll
        for (int gg = 0; gg < 2; gg++)
            ldsm_x4(b[slot][gg], bB + (b_row + gg * 16) * ASTRIDE + ks * 32 + b_koff);
    };

    // stage 0 ready: groups committed {0,1}; wait(1) -> group 0 complete.
    CP_WAIT(1);
    __syncthreads();
    ldfrags(0, smem0, smem0 + A_STAGE, 0);

    int cur = 0;
    for (int it = 0; it < KIT; it++) {
        uint32_t aB = smem0 + (it % STAGES) * STG_B;
        uint32_t bB = aB + A_STAGE;

#pragma unroll
        for (int ks = 0; ks < 4; ks++) {
            int nxt = cur ^ 1;
            if (ks < 3) {
                ldfrags(nxt, aB, bB, ks + 1);
            } else if (it + 1 < KIT) {
                // SOUND transition: commit the refill FIRST so CP_WAIT(1)
                // proves stage it+1 (group it+1) is complete.
                // Buffer (it+2)%3 overwrite is safe: stage it-1 reads all
                // precede the previous transition's __syncthreads().
                if (it + 2 < KIT) issue(it + 2);
                CP_COMMIT();
                CP_WAIT(1);            // groups <= it+1 complete
                __syncthreads();       // cross-thread visibility of stage it+1
                uint32_t aB2 = smem0 + ((it + 1) % STAGES) * STG_B;
                ldfrags(nxt, aB2, aB2 + A_STAGE, 0);
            }
#pragma unroll
            for (int g = 0; g < 4; g++)
#pragma unroll
                for (int f = 0; f < 4; f++)
                    mma_f16(acc[f][g], a[cur][f], b[cur][g >> 1] + (g & 1) * 2);
            cur = nxt;
        }
    }

    // ---------------- epilogue: dequant + bias ----------------
    int lr = lane >> 2;
    int lc2 = (lane & 3) * 2;
#pragma unroll
    for (int f = 0; f < 4; f++) {
        int gm = pid_m * BM + wm * 64 + f * 16 + lr;
        float* o0 = out + (size_t)gm * NTOT + pid_n * BN;
        float* o1 = o0 + (size_t)8 * NTOT;
#pragma unroll
        for (int g = 0; g < 4; g++) {
            int nc = wn * 32 + g * 8 + lc2;
            int gn = pid_n * BN + nc;
            float w0 = __ldg(wscale + gn), w1 = __ldg(wscale + gn + 1);
            float b0 = __ldg(bias + gn),   b1 = __ldg(bias + gn + 1);
            float2 r0, r1;
            r0.x = fmaf(acc[f][g][0], w0, b0);
            r0.y = fmaf(acc[f][g][1], w1, b1);
            r1.x = fmaf(acc[f][g][2], w0, b0);
            r1.y = fmaf(acc[f][g][3], w1, b1);
            *(float2*)(o0 + nc) = r0;
            *(float2*)(o1 + nc) = r1;
        }
    }
}

// ---------------- launch ----------------
extern "C" void kernel_launch(void* const* d_in, const int* in_sizes, int n_in,
                              void* d_out, int out_size) {
    const float* x      = (const float*)d_in[0];
    const int*   wq     = (const int*)d_in[1];
    const float* wscale = (const float*)d_in[2];
    const float* bias   = (const float*)d_in[3];
    float* out = (float*)d_out;

    cudaFuncSetAttribute(gemm_kernel, cudaFuncAttributeMaxDynamicSharedMemorySize, SMEM_TOTAL);

    conv_kernel<<<49152, 256>>>(x, wq);
    gemm_kernel<<<8192, 256, SMEM_TOTAL>>>(out, wscale, bias);
}

// round 13
// speedup vs baseline: 2.4184x; 1.0442x over previous
#include <cuda_runtime.h>
#include <cuda_fp16.h>
#include <cstdint>
#include <cstddef>

#define MTOT 8192
#define KTOT 4096
#define NTOT 16384

#define BM 128
#define BN 128
#define BK 64
#define STAGES 3
#define KIT (KTOT / BK)            // 64
#define ASTRIDE 144
#define A_STAGE (128 * ASTRIDE)
#define B_STAGE (128 * ASTRIDE)
#define STG_B (A_STAGE + B_STAGE)  // 36864
#define SMEM_TOTAL (STAGES * STG_B) // 110592 per CTA, x2 CTAs/SM

// ---------------- scratch ----------------
__device__ __half g_xh[(size_t)MTOT * KTOT];
__device__ __half g_wh[(size_t)NTOT * KTOT];

// ---------------- PTX helpers ----------------
__device__ __forceinline__ uint32_t smem_u32(const void* p) {
    uint32_t a;
    asm("{ .reg .u64 t; cvta.to.shared.u64 t, %1; cvt.u32.u64 %0, t; }" : "=r"(a) : "l"(p));
    return a;
}
#define CP16(dst, src) \
    asm volatile("cp.async.cg.shared.global [%0], [%1], 16;" :: "r"(dst), "l"(src) : "memory")
#define CP_COMMIT() asm volatile("cp.async.commit_group;" ::: "memory")
#define CP_WAIT(n)  asm volatile("cp.async.wait_group %0;" :: "n"(n) : "memory")

__device__ __forceinline__ void ldsm_x4(uint32_t* r, uint32_t addr) {
    asm volatile("ldmatrix.sync.aligned.m8n8.x4.shared.b16 {%0,%1,%2,%3}, [%4];"
                 : "=r"(r[0]), "=r"(r[1]), "=r"(r[2]), "=r"(r[3]) : "r"(addr));
}
__device__ __forceinline__ void mma_f16(float* d, const uint32_t* a, const uint32_t* b) {
    asm volatile(
        "mma.sync.aligned.m16n8k16.row.col.f32.f16.f16.f32 "
        "{%0,%1,%2,%3}, {%4,%5,%6,%7}, {%8,%9}, {%0,%1,%2,%3};"
        : "+f"(d[0]), "+f"(d[1]), "+f"(d[2]), "+f"(d[3])
        : "r"(a[0]), "r"(a[1]), "r"(a[2]), "r"(a[3]), "r"(b[0]), "r"(b[1]));
}

// ---------------- fused preprocessing ----------------
__global__ void __launch_bounds__(256) conv_kernel(
    const float* __restrict__ x, const int* __restrict__ wq)
{
    int bid = blockIdx.x;
    if (bid < 16384) {
        size_t idx = (size_t)bid * 256 + threadIdx.x;
        const float4* xi = (const float4*)x;
        float4 v0 = xi[idx * 2];
        float4 v1 = xi[idx * 2 + 1];
        __half2 h[4];
        h[0] = __float22half2_rn(make_float2(v0.x, v0.y));
        h[1] = __float22half2_rn(make_float2(v0.z, v0.w));
        h[2] = __float22half2_rn(make_float2(v1.x, v1.y));
        h[3] = __float22half2_rn(make_float2(v1.z, v1.w));
        ((uint4*)g_xh)[idx] = *(uint4*)h;
    } else {
        size_t idx = (size_t)(bid - 16384) * 256 + threadIdx.x;
        const int4* wi = (const int4*)wq;
        int4 v0 = wi[idx * 2];
        int4 v1 = wi[idx * 2 + 1];
        __half h[8];
        h[0] = __int2half_rn(v0.x); h[1] = __int2half_rn(v0.y);
        h[2] = __int2half_rn(v0.z); h[3] = __int2half_rn(v0.w);
        h[4] = __int2half_rn(v1.x); h[5] = __int2half_rn(v1.y);
        h[6] = __int2half_rn(v1.z); h[7] = __int2half_rn(v1.w);
        ((uint4*)g_wh)[idx] = *(uint4*)h;
    }
}

// ---------------- GEMM: 128x128, 2 CTAs/SM, reg-dbuf frags, hoisted refill ----------------
__global__ void __launch_bounds__(256, 2) gemm_kernel(
    float* __restrict__ out, const float* __restrict__ wscale,
    const float* __restrict__ bias)
{
    extern __shared__ uint8_t smem[];

    int tid = threadIdx.x;
    int wid = tid >> 5;
    int lane = tid & 31;
    int wm = wid >> 2;          // 0..1 (64 m rows)
    int wn = wid & 3;           // 0..3 (32 n cols)

    // GM=8 M-grouped raster over 64(m) x 128(n) tile grid
    int gid = blockIdx.x;
    int group = gid >> 10;
    int rem = gid & 1023;
    int pid_m = group * 8 + (rem & 7);
    int pid_n = rem >> 3;

    const __half* Ab = g_xh + (size_t)pid_m * BM * KTOT;
    const __half* Bb = g_wh + (size_t)pid_n * BN * KTOT;

    uint32_t smem0 = smem_u32(smem);

    auto issue = [&](int it) {
        uint32_t st = smem0 + (it % STAGES) * STG_B;
        int k0 = it * BK;
        int row = tid >> 3;
        int col = tid & 7;
        const __half* Asrc = Ab + (size_t)row * KTOT + k0 + col * 8;
        const __half* Bsrc = Bb + (size_t)row * KTOT + k0 + col * 8;
        uint32_t Adst = st + row * ASTRIDE + col * 16;
        uint32_t Bdst = st + A_STAGE + row * ASTRIDE + col * 16;
#pragma unroll
        for (int j = 0; j < 4; j++)
            CP16(Adst + j * 32 * ASTRIDE, Asrc + (size_t)j * 32 * KTOT);
#pragma unroll
        for (int j = 0; j < 4; j++)
            CP16(Bdst + j * 32 * ASTRIDE, Bsrc + (size_t)j * 32 * KTOT);
    };

    // prologue: issue stages 0,1
    issue(0); CP_COMMIT();
    issue(1); CP_COMMIT();

    float acc[4][4][4];
#pragma unroll
    for (int f = 0; f < 4; f++)
#pragma unroll
        for (int g = 0; g < 4; g++)
#pragma unroll
            for (int e = 0; e < 4; e++) acc[f][g][e] = 0.f;

    int j8 = lane >> 3;
    int r8 = lane & 7;
    int a_row = wm * 64 + (j8 & 1) * 8 + r8;
    int a_koff = (j8 >> 1) * 16;
    int b_row = wn * 32 + (j8 >> 1) * 8 + r8;
    int b_koff = (j8 & 1) * 16;

    uint32_t a[2][4][4], b[2][2][4];

    auto ldfrags = [&](int slot, uint32_t aB, uint32_t bB, int ks) {
#pragma unroll
        for (int f = 0; f < 4; f++)
            ldsm_x4(a[slot][f], aB + (a_row + f * 16) * ASTRIDE + ks * 32 + a_koff);
#pragma unroll
        for (int gg = 0; gg < 2; gg++)
            ldsm_x4(b[slot][gg], bB + (b_row + gg * 16) * ASTRIDE + ks * 32 + b_koff);
    };

    // stage 0 ready: groups committed {0,1}; wait(1) -> group 0 complete.
    CP_WAIT(1);
    __syncthreads();
    ldfrags(0, smem0, smem0 + A_STAGE, 0);

    int cur = 0;
    for (int it = 0; it < KIT; it++) {
        uint32_t aB = smem0 + (it % STAGES) * STG_B;
        uint32_t bB = aB + A_STAGE;

#pragma unroll
        for (int ks = 0; ks < 4; ks++) {
            int nxt = cur ^ 1;
            if (ks < 3) {
                ldfrags(nxt, aB, bB, ks + 1);
            } else if (it + 1 < KIT) {
                // Refill was already committed at ks==0 of this iteration, so
                // committed groups here = {0..it+2}; CP_WAIT(1) proves stage
                // it+1 (group it+1) complete. Buffer (it+2)%3 overwrite was
                // safe: stage it-1 reads preceded the previous transition's
                // __syncthreads().
                CP_WAIT(1);
                __syncthreads();
                uint32_t aB2 = smem0 + ((it + 1) % STAGES) * STG_B;
                ldfrags(nxt, aB2, aB2 + A_STAGE, 0);
            }
#pragma unroll
            for (int g = 0; g < 4; g++)
#pragma unroll
                for (int f = 0; f < 4; f++)
                    mma_f16(acc[f][g], a[cur][f], b[cur][g >> 1] + (g & 1) * 2);
            cur = nxt;
            if (ks == 0) {
                // hoisted refill: far from the wait, off the barrier window
                if (it + 2 < KIT) issue(it + 2);
                CP_COMMIT();
            }
        }
    }

    // ---------------- epilogue: dequant + bias ----------------
    int lr = lane >> 2;
    int lc2 = (lane & 3) * 2;
#pragma unroll
    for (int f = 0; f < 4; f++) {
        int gm = pid_m * BM + wm * 64 + f * 16 + lr;
        float* o0 = out + (size_t)gm * NTOT + pid_n * BN;
        float* o1 = o0 + (size_t)8 * NTOT;
#pragma unroll
        for (int g = 0; g < 4; g++) {
            int nc = wn * 32 + g * 8 + lc2;
            int gn = pid_n * BN + nc;
            float w0 = __ldg(wscale + gn), w1 = __ldg(wscale + gn + 1);
            float b0 = __ldg(bias + gn),   b1 = __ldg(bias + gn + 1);
            float2 r0, r1;
            r0.x = fmaf(acc[f][g][0], w0, b0);
            r0.y = fmaf(acc[f][g][1], w1, b1);
            r1.x = fmaf(acc[f][g][2], w0, b0);
            r1.y = fmaf(acc[f][g][3], w1, b1);
            *(float2*)(o0 + nc) = r0;
            *(float2*)(o1 + nc) = r1;
        }
    }
}

// ---------------- launch ----------------
extern "C" void kernel_launch(void* const* d_in, const int* in_sizes, int n_in,
                              void* d_out, int out_size) {
    const float* x      = (const float*)d_in[0];
    const int*   wq     = (const int*)d_in[1];
    const float* wscale = (const float*)d_in[2];
    const float* bias   = (const float*)d_in[3];
    float* out = (float*)d_out;

    cudaFuncSetAttribute(gemm_kernel, cudaFuncAttributeMaxDynamicSharedMemorySize, SMEM_TOTAL);

    conv_kernel<<<49152, 256>>>(x, wq);
    gemm_kernel<<<8192, 256, SMEM_TOTAL>>>(out, wscale, bias);
}